// round 10
// baseline (speedup 1.0000x reference)
#include <cuda_runtime.h>
#include <cstdint>

// CrossModalCenterLoss — FINAL converged kernel.
//
//   loss = (sum_b clip(||x_b - centers[labels_b]||^2, 1e-12, 1e12)) / B
//        + (C-1) * 1e-12
//
// Inputs: x [4096,256] f32, labels [4096] int32, centers [10000,256] f32.
// Output: scalar f32.
//
// Key insight: the reference's [B,C] distance matrix is masked down to one
// column per row before the clamp, so the GEMM is dead work; the real
// computation is 4096 gathered squared distances plus an exact
// (C-1)*1e-12 constant from the clamped zeros.
//
// Measured convergence (GB300, 9 structural variants): 512 blocks x 512
// threads (8192 warps, one half-row per warp), single graph node, private
// per-block slot + ticket counter, last block gathers 512 slots with 4
// LDG.128/lane. Three independent runs of this shape hit 8.672us; every
// deviation (128/1024/2048 blocks, 4096 warps, same-address atomic chain,
// separate finalizer node) measured equal or worse (+0.03..+4.4us). The
// timed total is a per-replay floor (graph-launch overhead over an
// L2-resident ~2us kernel); residual in-kernel deltas are below the
// 0.256us timer quantum.
//
// The [1e-12,1e12] clamp is inactive for this data (dist ~ 2*D ~ 512);
// summing raw distances perturbs the result by < 1e-12 abs — below fp32
// ulp at that magnitude. The floor term is added exactly in the finalizer.

#define BATCH_N   4096
#define NUM_CLS   10000
#define FEAT_D    256
#define CLAMP_LO  1e-12f
#define WARPS_PER_BLK 16
#define GRID_BLKS 512

__device__ __align__(16) float g_part[GRID_BLKS];
__device__ unsigned g_count = 0u;

__global__ __launch_bounds__(512) void cmcl_main(
    const float* __restrict__ x,
    const int* __restrict__ labels,
    const float* __restrict__ centers,
    float* __restrict__ out)
{
    const int warp = threadIdx.x >> 5;
    const int lane = threadIdx.x & 31;
    const int g    = blockIdx.x * WARPS_PER_BLK + warp;   // 0..8191
    const int row  = g >> 1;
    const int half = g & 1;

    // Label broadcast load (center gather depends on it); the x load is
    // independent and overlaps it.
    int lbl = labels[row];
    const float4* xr = reinterpret_cast<const float4*>(
        x + (size_t)row * FEAT_D + half * 128);
    float4 a = xr[lane];

    lbl = max(0, min(NUM_CLS - 1, lbl));                  // never fault
    const float4* cr = reinterpret_cast<const float4*>(
        centers + (size_t)lbl * FEAT_D + half * 128);
    float4 b = cr[lane];

    float d, acc;
    d = a.x - b.x; acc = d * d;
    d = a.y - b.y; acc = fmaf(d, d, acc);
    d = a.z - b.z; acc = fmaf(d, d, acc);
    d = a.w - b.w; acc = fmaf(d, d, acc);

    // Warp reduction -> half-row partial distance.
    #pragma unroll
    for (int o = 16; o > 0; o >>= 1)
        acc += __shfl_xor_sync(0xffffffffu, acc, o);

    __shared__ float warp_sums[WARPS_PER_BLK];
    if (lane == 0) warp_sums[warp] = acc;
    __syncthreads();

    if (warp == 0) {
        float v = (lane < WARPS_PER_BLK) ? warp_sums[lane] : 0.0f;
        #pragma unroll
        for (int o = 8; o > 0; o >>= 1)
            v += __shfl_xor_sync(0xffffffffu, v, o);

        unsigned ticket = 0u;
        if (lane == 0) {
            g_part[blockIdx.x] = v;        // private slot: no serialization
            __threadfence();               // slot visible before ticket
            ticket = atomicAdd(&g_count, 1u);
        }
        ticket = __shfl_sync(0xffffffffu, ticket, 0);

        if (ticket == (unsigned)(GRID_BLKS - 1)) {
            // Last block: all other slots visible (fence + ticket).
            // Gather 512 floats as 128 float4 = 4 LDG.128 per lane.
            const float4* p4 = reinterpret_cast<const float4*>(g_part);
            float s = 0.0f;
            #pragma unroll
            for (int i = 0; i < GRID_BLKS / 128; i++) {   // 4 iterations
                float4 t = __ldcg(&p4[i * 32 + lane]);
                s += (t.x + t.y) + (t.z + t.w);
            }
            #pragma unroll
            for (int o = 16; o > 0; o >>= 1)
                s += __shfl_xor_sync(0xffffffffu, s, o);
            if (lane == 0) {
                out[0] = s * (1.0f / (float)BATCH_N)
                       + (float)(NUM_CLS - 1) * CLAMP_LO;
                g_count = 0u;              // reset for next graph replay
            }
        }
    }
}

extern "C" void kernel_launch(void* const* d_in, const int* in_sizes, int n_in,
                              void* d_out, int out_size) {
    const float* x       = (const float*)d_in[0];
    const int*   labels  = (const int*)d_in[1];
    const float* centers = (const float*)d_in[2];
    float*       out     = (float*)d_out;
    (void)in_sizes; (void)n_in; (void)out_size;

    cmcl_main<<<GRID_BLKS, 512>>>(x, labels, centers, out);
}

// round 11
// speedup vs baseline: 1.0257x; 1.0257x over previous
#include <cuda_runtime.h>
#include <cstdint>

// CrossModalCenterLoss — FINAL converged kernel (unchanged from R9/R10).
//
//   loss = (sum_b clip(||x_b - centers[labels_b]||^2, 1e-12, 1e12)) / B
//        + (C-1) * 1e-12
//
// Inputs: x [4096,256] f32, labels [4096] int32, centers [10000,256] f32.
// Output: scalar f32.
//
// Algorithmic core: the reference's [B,C] distance matrix is masked down
// to one column per row BEFORE the clamp, so the einsum GEMM is dead work.
// The real computation is 4096 gathered squared distances (O(B*D), ~8MB
// traffic) plus an exact (C-1)*1e-12 constant from the clamped zeros —
// ~1000x less work than the reference.
//
// Measurement summary (GB300, 10 rounds): A/A repeats of this exact source
// give 8.672 and 8.928us -> noise band +-0.256us (timer quantum). All
// single-node variants (128..2048 blocks, 4096/8192 warps, three tail
// schemes) fall inside 8.672-8.96us; a dependent second graph node costs
// +4.3us. Steady-state replay keeps the working set L2-resident; the
// timed total is a per-replay floor (graph-launch overhead over a ~2us
// latency-bound kernel), not addressable from inside kernel_launch.
//
// The [1e-12,1e12] clamp is inactive for this data (dist ~ 2*D ~ 512);
// summing raw distances perturbs the result by < 1e-12 abs — below fp32
// ulp at that magnitude. The floor term is added exactly in the finalizer.

#define BATCH_N   4096
#define NUM_CLS   10000
#define FEAT_D    256
#define CLAMP_LO  1e-12f
#define WARPS_PER_BLK 16
#define GRID_BLKS 512

__device__ __align__(16) float g_part[GRID_BLKS];
__device__ unsigned g_count = 0u;

__global__ __launch_bounds__(512) void cmcl_main(
    const float* __restrict__ x,
    const int* __restrict__ labels,
    const float* __restrict__ centers,
    float* __restrict__ out)
{
    const int warp = threadIdx.x >> 5;
    const int lane = threadIdx.x & 31;
    const int g    = blockIdx.x * WARPS_PER_BLK + warp;   // 0..8191
    const int row  = g >> 1;
    const int half = g & 1;

    // Label broadcast load (center gather depends on it); the x load is
    // independent and overlaps it.
    int lbl = labels[row];
    const float4* xr = reinterpret_cast<const float4*>(
        x + (size_t)row * FEAT_D + half * 128);
    float4 a = xr[lane];

    lbl = max(0, min(NUM_CLS - 1, lbl));                  // never fault
    const float4* cr = reinterpret_cast<const float4*>(
        centers + (size_t)lbl * FEAT_D + half * 128);
    float4 b = cr[lane];

    float d, acc;
    d = a.x - b.x; acc = d * d;
    d = a.y - b.y; acc = fmaf(d, d, acc);
    d = a.z - b.z; acc = fmaf(d, d, acc);
    d = a.w - b.w; acc = fmaf(d, d, acc);

    // Warp reduction -> half-row partial distance.
    #pragma unroll
    for (int o = 16; o > 0; o >>= 1)
        acc += __shfl_xor_sync(0xffffffffu, acc, o);

    __shared__ float warp_sums[WARPS_PER_BLK];
    if (lane == 0) warp_sums[warp] = acc;
    __syncthreads();

    if (warp == 0) {
        float v = (lane < WARPS_PER_BLK) ? warp_sums[lane] : 0.0f;
        #pragma unroll
        for (int o = 8; o > 0; o >>= 1)
            v += __shfl_xor_sync(0xffffffffu, v, o);

        unsigned ticket = 0u;
        if (lane == 0) {
            g_part[blockIdx.x] = v;        // private slot: no serialization
            __threadfence();               // slot visible before ticket
            ticket = atomicAdd(&g_count, 1u);
        }
        ticket = __shfl_sync(0xffffffffu, ticket, 0);

        if (ticket == (unsigned)(GRID_BLKS - 1)) {
            // Last block: all other slots visible (fence + ticket).
            // Gather 512 floats as 128 float4 = 4 LDG.128 per lane.
            const float4* p4 = reinterpret_cast<const float4*>(g_part);
            float s = 0.0f;
            #pragma unroll
            for (int i = 0; i < GRID_BLKS / 128; i++) {   // 4 iterations
                float4 t = __ldcg(&p4[i * 32 + lane]);
                s += (t.x + t.y) + (t.z + t.w);
            }
            #pragma unroll
            for (int o = 16; o > 0; o >>= 1)
                s += __shfl_xor_sync(0xffffffffu, s, o);
            if (lane == 0) {
                out[0] = s * (1.0f / (float)BATCH_N)
                       + (float)(NUM_CLS - 1) * CLAMP_LO;
                g_count = 0u;              // reset for next graph replay
            }
        }
    }
}

extern "C" void kernel_launch(void* const* d_in, const int* in_sizes, int n_in,
                              void* d_out, int out_size) {
    const float* x       = (const float*)d_in[0];
    const int*   labels  = (const int*)d_in[1];
    const float* centers = (const float*)d_in[2];
    float*       out     = (float*)d_out;
    (void)in_sizes; (void)n_in; (void)out_size;

    cmcl_main<<<GRID_BLKS, 512>>>(x, labels, centers, out);
}

// round 12
// speedup vs baseline: 1.0295x; 1.0037x over previous
#include <cuda_runtime.h>
#include <cstdint>

// CrossModalCenterLoss — FINAL converged kernel (unchanged; 3x A/A-confirmed).
//
//   loss = (sum_b clip(||x_b - centers[labels_b]||^2, 1e-12, 1e12)) / B
//        + (C-1) * 1e-12
//
// Inputs: x [4096,256] f32, labels [4096] int32, centers [10000,256] f32.
// Output: scalar f32.
//
// Algorithmic core: the reference's [B,C] distance matrix is masked down
// to one column per row BEFORE the clamp, so the einsum GEMM is dead work.
// The real computation is 4096 gathered squared distances (O(B*D), ~8MB
// traffic) plus an exact (C-1)*1e-12 constant from the clamped zeros —
// ~1000x less work than the reference.
//
// Measurement summary (GB300, 11 rounds): this exact source measured
// 8.672 / 8.928 / 8.704us on three independent runs -> noise band
// +-0.256us (timer quantum). All single-node variants (128..2048 blocks,
// 1024..8192 warps, three reduction-tail schemes, regs 16..40) fall inside
// 8.67-8.96us; a dependent second graph node costs +4.3us. Steady-state
// replay keeps the 14MB working set L2-resident; the timed total is a
// per-replay floor (graph-launch overhead over a ~2us latency-bound
// kernel), not addressable from inside kernel_launch.
//
// The [1e-12,1e12] clamp is inactive for this data (dist ~ 2*D ~ 512);
// summing raw distances perturbs the result by < 1e-12 abs — below fp32
// ulp at that magnitude. The floor term is added exactly in the finalizer.

#define BATCH_N   4096
#define NUM_CLS   10000
#define FEAT_D    256
#define CLAMP_LO  1e-12f
#define WARPS_PER_BLK 16
#define GRID_BLKS 512

__device__ __align__(16) float g_part[GRID_BLKS];
__device__ unsigned g_count = 0u;

__global__ __launch_bounds__(512) void cmcl_main(
    const float* __restrict__ x,
    const int* __restrict__ labels,
    const float* __restrict__ centers,
    float* __restrict__ out)
{
    const int warp = threadIdx.x >> 5;
    const int lane = threadIdx.x & 31;
    const int g    = blockIdx.x * WARPS_PER_BLK + warp;   // 0..8191
    const int row  = g >> 1;
    const int half = g & 1;

    // Label broadcast load (center gather depends on it); the x load is
    // independent and overlaps it.
    int lbl = labels[row];
    const float4* xr = reinterpret_cast<const float4*>(
        x + (size_t)row * FEAT_D + half * 128);
    float4 a = xr[lane];

    lbl = max(0, min(NUM_CLS - 1, lbl));                  // never fault
    const float4* cr = reinterpret_cast<const float4*>(
        centers + (size_t)lbl * FEAT_D + half * 128);
    float4 b = cr[lane];

    float d, acc;
    d = a.x - b.x; acc = d * d;
    d = a.y - b.y; acc = fmaf(d, d, acc);
    d = a.z - b.z; acc = fmaf(d, d, acc);
    d = a.w - b.w; acc = fmaf(d, d, acc);

    // Warp reduction -> half-row partial distance.
    #pragma unroll
    for (int o = 16; o > 0; o >>= 1)
        acc += __shfl_xor_sync(0xffffffffu, acc, o);

    __shared__ float warp_sums[WARPS_PER_BLK];
    if (lane == 0) warp_sums[warp] = acc;
    __syncthreads();

    if (warp == 0) {
        float v = (lane < WARPS_PER_BLK) ? warp_sums[lane] : 0.0f;
        #pragma unroll
        for (int o = 8; o > 0; o >>= 1)
            v += __shfl_xor_sync(0xffffffffu, v, o);

        unsigned ticket = 0u;
        if (lane == 0) {
            g_part[blockIdx.x] = v;        // private slot: no serialization
            __threadfence();               // slot visible before ticket
            ticket = atomicAdd(&g_count, 1u);
        }
        ticket = __shfl_sync(0xffffffffu, ticket, 0);

        if (ticket == (unsigned)(GRID_BLKS - 1)) {
            // Last block: all other slots visible (fence + ticket).
            // Gather 512 floats as 128 float4 = 4 LDG.128 per lane.
            const float4* p4 = reinterpret_cast<const float4*>(g_part);
            float s = 0.0f;
            #pragma unroll
            for (int i = 0; i < GRID_BLKS / 128; i++) {   // 4 iterations
                float4 t = __ldcg(&p4[i * 32 + lane]);
                s += (t.x + t.y) + (t.z + t.w);
            }
            #pragma unroll
            for (int o = 16; o > 0; o >>= 1)
                s += __shfl_xor_sync(0xffffffffu, s, o);
            if (lane == 0) {
                out[0] = s * (1.0f / (float)BATCH_N)
                       + (float)(NUM_CLS - 1) * CLAMP_LO;
                g_count = 0u;              // reset for next graph replay
            }
        }
    }
}

extern "C" void kernel_launch(void* const* d_in, const int* in_sizes, int n_in,
                              void* d_out, int out_size) {
    const float* x       = (const float*)d_in[0];
    const int*   labels  = (const int*)d_in[1];
    const float* centers = (const float*)d_in[2];
    float*       out     = (float*)d_out;
    (void)in_sizes; (void)n_in; (void)out_size;

    cmcl_main<<<GRID_BLKS, 512>>>(x, labels, centers, out);
}